// round 6
// baseline (speedup 1.0000x reference)
#include <cuda_runtime.h>
#include <math.h>

// Problem constants (shapes fixed by the dataset)
#define NN 50000
#define NE 800000
#define D0 64   // x features
#define D1 96   // hidden
#define D2 64   // out

#define NB 256      // blocks in persistent build kernel (256 divides 2^32)
#define NT 256      // threads per block

// ---------------- scratch (device globals: no allocation allowed) ----------
__device__ int      g_is64;
__device__ int      g_csr[NE];
__device__ int      g_cnt[NN];
__device__ int      g_row[NN + 1];
__device__ int      g_cur[NN];
__device__ float    g_dis[NN];
__device__ int      g_bsum[NB];
__device__ int      g_bpre[NB];
__device__ unsigned g_barrier_ctr;   // monotonic across launches (replay-safe)
__device__ float    g_hs1[NN * D1];  // (x@W1)*dis[row]
__device__ float    g_h  [NN * D1];  // relu(layer1)
__device__ float    g_hs2[NN * D2];  // (h@W2)*dis[row]

// ---------------- software grid barrier (persistent kernel) ----------------
// Monotonic counter, never reset: each barrier consumes exactly NB arrivals,
// so arrival targets stay NB-aligned across graph replays. Wrap-safe compare.
__device__ __forceinline__ void gbar() {
    __threadfence();            // publish this thread's writes before arriving
    __syncthreads();
    if (threadIdx.x == 0) {
        unsigned old = atomicAdd(&g_barrier_ctr, 1u);
        unsigned target = (old & ~(unsigned)(NB - 1)) + NB;
        while ((int)(*(volatile unsigned*)&g_barrier_ctr - target) < 0)
            __nanosleep(64);
        __threadfence();
    }
    __syncthreads();
}

// ---------------- launch 0: fused CSR build (persistent) -------------------
// Phase A: zero g_cnt + dtype detect.  Phase B: in-degree histogram.
// Phase C: two-level exclusive scan -> g_row/g_cur + g_dis.
// dtype detect: values in [0,50000); for little-endian int64 every odd 32-bit
// word of the first 1024 entries is 0; for int32 they are random edge ids.
__global__ void __launch_bounds__(NT, 8) k_build(const void* __restrict__ ep) {
    int t   = threadIdx.x;
    int blk = blockIdx.x;
    int gid = blk * NT + t;

    // ---- Phase A: zero histogram; block 0 detects dtype
    if (gid < NN) g_cnt[gid] = 0;
    if (blk == 0) {
        const int* e = (const int*)ep;
        int local = 0;
#pragma unroll
        for (int q = 0; q < 4; q++) local |= e[2 * (t * 4 + q) + 1];
        __shared__ int nz;
        if (t == 0) nz = 0;
        __syncthreads();
        if (local) atomicOr(&nz, 1);
        __syncthreads();
        if (t == 0) g_is64 = (nz == 0) ? 1 : 0;
    }
    gbar();

    // ---- Phase B: histogram (2 edges per iteration, vector loads)
    {
        int is64 = __ldcg(&g_is64);
        if (is64) {
            const longlong2* p = (const longlong2*)ep;
            for (int i = gid; i < NE / 2; i += NB * NT) {
                longlong2 dd = p[NE / 2 + i];           // dst half
                atomicAdd(&g_cnt[(int)dd.x], 1);
                atomicAdd(&g_cnt[(int)dd.y], 1);
            }
        } else {
            const int2* p = (const int2*)ep;
            for (int i = gid; i < NE / 2; i += NB * NT) {
                int2 dd = p[NE / 2 + i];
                atomicAdd(&g_cnt[dd.x], 1);
                atomicAdd(&g_cnt[dd.y], 1);
            }
        }
    }
    gbar();

    // ---- Phase C1: block-local scan of 256 counts (one node per thread)
    __shared__ int sc[NT];
    int c = (gid < NN) ? __ldcg(&g_cnt[gid]) : 0;
    sc[t] = c;
    __syncthreads();
#pragma unroll
    for (int off = 1; off < NT; off <<= 1) {
        int v = sc[t];
        int a = (t >= off) ? sc[t - off] : 0;
        __syncthreads();
        sc[t] = v + a;
        __syncthreads();
    }
    int incl = sc[t];
    if (t == NT - 1) g_bsum[blk] = incl;   // block total
    gbar();

    // ---- Phase C2: block 0 scans the 256 block totals
    if (blk == 0) {
        int s = __ldcg(&g_bsum[t]);
        sc[t] = s;
        __syncthreads();
#pragma unroll
        for (int off = 1; off < NT; off <<= 1) {
            int v = sc[t];
            int a = (t >= off) ? sc[t - off] : 0;
            __syncthreads();
            sc[t] = v + a;
            __syncthreads();
        }
        g_bpre[t] = sc[t] - s;   // exclusive prefix of block sums
    }
    gbar();

    // ---- Phase C3: write row/cur/dis
    if (gid < NN) {
        int base = __ldcg(&g_bpre[blk]);
        int excl = base + incl - c;
        g_row[gid] = excl;
        g_cur[gid] = excl;
        g_dis[gid] = rsqrtf((float)c + 1.0f);
    }
    if (gid == 0) g_row[NN] = NE;
}

// ---------------- launch 1: CSR scatter ------------------------------------
__global__ void k_scatter(const void* __restrict__ ep) {
    int e = blockIdx.x * blockDim.x + threadIdx.x;
    if (e >= NE) return;
    int s, d;
    if (g_is64) {
        const long long* p = (const long long*)ep;
        s = (int)p[e];
        d = (int)p[NE + e];
    } else {
        const int* p = (const int*)ep;
        s = p[e];
        d = p[NE + e];
    }
    int pos = atomicAdd(&g_cur[d], 1);
    g_csr[pos] = s;
}

// ---------------- GEMM: HS[row][c] = dis[row] * sum_k X[row][k]*W[k][c] -----
// 256 threads = 8 warps, 64 rows/block (8 rows/warp); W + 64 X rows staged in
// shared via float4. Lane l owns columns l, l+32, (l+64). Conflict-free LDS.
template <int IN, int OUT>
__global__ void k_gemm(const float* __restrict__ X, const float* __restrict__ W,
                       float* __restrict__ HS) {
    constexpr int CPL = OUT / 32;
    constexpr int RW  = 8;                 // rows per warp
    __shared__ float Ws[IN * OUT];
    __shared__ float Xs[64 * IN];
    int t = threadIdx.x;
    // stage W (float4)
    {
        const float4* W4 = (const float4*)W;
        float4* Ws4 = (float4*)Ws;
        for (int i = t; i < IN * OUT / 4; i += 256) Ws4[i] = W4[i];
    }
    int row0 = blockIdx.x * 64;
    // stage X rows (float4)
    {
        constexpr int K4 = IN / 4;
        const float4* X4 = (const float4*)X;
        float4* Xs4 = (float4*)Xs;
        for (int i = t; i < 64 * K4; i += 256) {
            int r = i / K4, k4 = i % K4;
            int gr = row0 + r;
            Xs4[i] = (gr < NN) ? X4[gr * K4 + k4]
                               : make_float4(0.f, 0.f, 0.f, 0.f);
        }
    }
    __syncthreads();

    int w = t >> 5, lane = t & 31;
    int rbase = w * RW;
    float acc[RW][CPL];
#pragma unroll
    for (int r = 0; r < RW; r++)
#pragma unroll
        for (int c = 0; c < CPL; c++) acc[r][c] = 0.0f;

#pragma unroll
    for (int k = 0; k < IN; k++) {
        float wv[CPL];
#pragma unroll
        for (int c = 0; c < CPL; c++) wv[c] = Ws[k * OUT + lane + 32 * c];
        float xv[RW];
#pragma unroll
        for (int r = 0; r < RW; r++) xv[r] = Xs[(rbase + r) * IN + k];
#pragma unroll
        for (int r = 0; r < RW; r++)
#pragma unroll
            for (int c = 0; c < CPL; c++) acc[r][c] = fmaf(xv[r], wv[c], acc[r][c]);
    }

#pragma unroll
    for (int r = 0; r < RW; r++) {
        int gr = row0 + rbase + r;
        if (gr < NN) {
            float d = g_dis[gr];
#pragma unroll
            for (int c = 0; c < CPL; c++)
                HS[gr * OUT + lane + 32 * c] = acc[r][c] * d;
        }
    }
}

// ---------------- Aggregation: one warp per node, 8-deep gather pipeline ---
// out[i][f] = act( dis[i]*(HS[i][f] + sum_{e: dst=i} HS[src_e][f]) + b[f] )
__device__ __forceinline__ float act_relu(float v)    { return fmaxf(v, 0.0f); }
__device__ __forceinline__ float act_sigmoid(float v) { return 1.0f / (1.0f + expf(-v)); }

template <int F, int ACT>
__global__ void k_agg(const float* __restrict__ HS, const float* __restrict__ b,
                      float* __restrict__ OUT) {
    int warp = (blockIdx.x * blockDim.x + threadIdx.x) >> 5;
    int lane = threadIdx.x & 31;
    if (warp >= NN) return;

    int beg = g_row[warp], end = g_row[warp + 1];

    if constexpr (F == 96) {
        constexpr int C4 = F / 4;  // 24 float4 columns; lanes 0..23 active
        const float4* H4 = (const float4*)HS;
        bool on = lane < C4;
        float4 acc = make_float4(0.f, 0.f, 0.f, 0.f);
        if (on) acc = H4[warp * C4 + lane];  // self loop

        int j = beg;
        for (; j + 8 <= end; j += 8) {
            int s[8];
#pragma unroll
            for (int q = 0; q < 8; q++) s[q] = g_csr[j + q];
            if (on) {
                float4 v[8];
#pragma unroll
                for (int q = 0; q < 8; q++) v[q] = H4[s[q] * C4 + lane];
#pragma unroll
                for (int q = 0; q < 8; q++) {
                    acc.x += v[q].x; acc.y += v[q].y;
                    acc.z += v[q].z; acc.w += v[q].w;
                }
            }
        }
        for (; j < end; j++) {
            int s0 = g_csr[j];
            if (on) {
                float4 v = H4[s0 * C4 + lane];
                acc.x += v.x; acc.y += v.y; acc.z += v.z; acc.w += v.w;
            }
        }
        if (on) {
            float d = g_dis[warp];
            float4 bb = ((const float4*)b)[lane];
            float4 o;
            if (ACT == 0) {
                o.x = act_relu(fmaf(d, acc.x, bb.x));
                o.y = act_relu(fmaf(d, acc.y, bb.y));
                o.z = act_relu(fmaf(d, acc.z, bb.z));
                o.w = act_relu(fmaf(d, acc.w, bb.w));
            } else {
                o.x = act_sigmoid(fmaf(d, acc.x, bb.x));
                o.y = act_sigmoid(fmaf(d, acc.y, bb.y));
                o.z = act_sigmoid(fmaf(d, acc.z, bb.z));
                o.w = act_sigmoid(fmaf(d, acc.w, bb.w));
            }
            ((float4*)OUT)[warp * C4 + lane] = o;
        }
    } else {  // F == 64
        constexpr int C2 = F / 2;  // 32 float2 columns, all lanes active
        const float2* H2 = (const float2*)HS;
        float2 acc = H2[warp * C2 + lane];  // self loop

        int j = beg;
        for (; j + 8 <= end; j += 8) {
            int s[8];
#pragma unroll
            for (int q = 0; q < 8; q++) s[q] = g_csr[j + q];
            float2 v[8];
#pragma unroll
            for (int q = 0; q < 8; q++) v[q] = H2[s[q] * C2 + lane];
#pragma unroll
            for (int q = 0; q < 8; q++) { acc.x += v[q].x; acc.y += v[q].y; }
        }
        for (; j < end; j++) {
            int s0 = g_csr[j];
            float2 v = H2[s0 * C2 + lane];
            acc.x += v.x; acc.y += v.y;
        }
        float d = g_dis[warp];
        float2 bb = ((const float2*)b)[lane];
        float2 o;
        if (ACT == 0) {
            o.x = act_relu(fmaf(d, acc.x, bb.x));
            o.y = act_relu(fmaf(d, acc.y, bb.y));
        } else {
            o.x = act_sigmoid(fmaf(d, acc.x, bb.x));
            o.y = act_sigmoid(fmaf(d, acc.y, bb.y));
        }
        ((float2*)OUT)[warp * C2 + lane] = o;
    }
}

// ---------------- launch ---------------------------------------------------
extern "C" void kernel_launch(void* const* d_in, const int* in_sizes, int n_in,
                              void* d_out, int out_size) {
    const float* x  = (const float*)d_in[0];
    const void*  ei = d_in[1];
    const float* W1 = (const float*)d_in[2];
    const float* b1 = (const float*)d_in[3];
    const float* W2 = (const float*)d_in[4];
    const float* b2 = (const float*)d_in[5];
    float* out = (float*)d_out;

    const int TB = 256;
    k_build<<<NB, NT>>>(ei);                                         // 0
    k_scatter<<<(NE + TB - 1) / TB, TB>>>(ei);                       // 1
    k_gemm<D0, D1><<<(NN + 63) / 64, 256>>>(x, W1, g_hs1);           // 2
    k_agg<D1, 0><<<(NN * 32 + TB - 1) / TB, TB>>>(g_hs1, b1, g_h);   // 3 <- ncu probe
    k_gemm<D1, D2><<<(NN + 63) / 64, 256>>>(g_h, W2, g_hs2);         // 4
    k_agg<D2, 1><<<(NN * 32 + TB - 1) / TB, TB>>>(g_hs2, b2, out);   // 5
}

// round 8
// speedup vs baseline: 21.1007x; 21.1007x over previous
#include <cuda_runtime.h>
#include <math.h>

// Problem constants (shapes fixed by the dataset)
#define NN 50000
#define NE 800000
#define D0 64   // x features
#define D1 96   // hidden
#define D2 64   // out

#define GRID 512    // persistent blocks; power of 2 (divides 2^32) for gbar
#define NT   256    // threads per block

// ---------------- scratch (device globals: no allocation allowed) ----------
__device__ int      g_csr[NE];
__device__ int      g_cnt[NN];
__device__ int      g_row[NN + 1];
__device__ int      g_cur[NN];
__device__ float    g_dis[NN];
__device__ int      g_bsum[GRID];
__device__ int      g_bpre[GRID];
__device__ unsigned g_barrier_ctr;   // monotonic across launches (replay-safe)
__device__ float    g_hs1[NN * D1];  // (x@W1)*dis[row]
__device__ float    g_h  [NN * D1];  // relu(layer1)
__device__ float    g_hs2[NN * D2];  // (h@W2)*dis[row]

__device__ __forceinline__ float act_relu(float v)    { return fmaxf(v, 0.0f); }
__device__ __forceinline__ float act_sigmoid(float v) { return 1.0f / (1.0f + expf(-v)); }

// ---------------- software grid barrier ------------------------------------
// Monotonic counter, never reset: each barrier consumes exactly GRID arrivals,
// so arrival targets stay GRID-aligned across graph replays. Wrap-safe.
__device__ __forceinline__ void gbar() {
    __threadfence();
    __syncthreads();
    if (threadIdx.x == 0) {
        unsigned old = atomicAdd(&g_barrier_ctr, 1u);
        unsigned target = (old & ~(unsigned)(GRID - 1)) + GRID;
        while ((int)(*(volatile unsigned*)&g_barrier_ctr - target) < 0)
            __nanosleep(64);
        __threadfence();
    }
    __syncthreads();
}

// ---------------- GEMM phase (device function) -----------------------------
// HS[row][c] = dis[row] * sum_k X[row][k]*W[k][c].
// W staged in smem ONCE per block; tiles of 32 rows grid-strided.
// 8 warps, 4 rows/warp; lane l owns cols l, l+32, (l+64). Conflict-free LDS.
template <int IN, int OUT>
__device__ void gemm_phase(const float* __restrict__ X, const float* __restrict__ W,
                           float* __restrict__ HS, float* sWs, float* sXs) {
    constexpr int CPL = OUT / 32;
    constexpr int K4  = IN / 4;
    int t = threadIdx.x;
    // stage W once (float4)
    for (int i = t; i < IN * OUT / 4; i += NT)
        ((float4*)sWs)[i] = ((const float4*)W)[i];

    int w = t >> 5, lane = t & 31;
    int rbase = w * 4;
    int ntile = (NN + 31) / 32;

    for (int tile = blockIdx.x; tile < ntile; tile += GRID) {
        __syncthreads();   // Ws ready (iter 0) / prior readers done with Xs
        int row0 = tile * 32;
        for (int i = t; i < 32 * K4; i += NT) {
            int r = i / K4, k4 = i % K4;
            int gr = row0 + r;
            ((float4*)sXs)[i] = (gr < NN) ? ((const float4*)X)[gr * K4 + k4]
                                          : make_float4(0.f, 0.f, 0.f, 0.f);
        }
        __syncthreads();

        float acc[4][CPL];
#pragma unroll
        for (int r = 0; r < 4; r++)
#pragma unroll
            for (int c = 0; c < CPL; c++) acc[r][c] = 0.0f;

#pragma unroll
        for (int k = 0; k < IN; k++) {
            float wv[CPL];
#pragma unroll
            for (int c = 0; c < CPL; c++) wv[c] = sWs[k * OUT + lane + 32 * c];
            float xv[4];
#pragma unroll
            for (int r = 0; r < 4; r++) xv[r] = sXs[(rbase + r) * IN + k];
#pragma unroll
            for (int r = 0; r < 4; r++)
#pragma unroll
                for (int c = 0; c < CPL; c++)
                    acc[r][c] = fmaf(xv[r], wv[c], acc[r][c]);
        }

#pragma unroll
        for (int r = 0; r < 4; r++) {
            int gr = row0 + rbase + r;
            if (gr < NN) {
                float d = g_dis[gr];
#pragma unroll
                for (int c = 0; c < CPL; c++)
                    HS[gr * OUT + lane + 32 * c] = acc[r][c] * d;
            }
        }
    }
}

// ---------------- Aggregation phase (device function) ----------------------
// out[i][f] = act( dis[i]*(HS[i][f] + sum_{e: dst=i} HS[src_e][f]) + b[f] )
// One warp per node, grid-strided; 4-deep gather pipeline (reg-pressure safe).
template <int F, int ACT>
__device__ void agg_phase(const float* __restrict__ HS, const float* __restrict__ b,
                          float* __restrict__ OUT) {
    int warp0 = (blockIdx.x * NT + threadIdx.x) >> 5;
    int lane  = threadIdx.x & 31;
    constexpr int WSTRIDE = GRID * NT / 32;   // 4096 warps

    for (int node = warp0; node < NN; node += WSTRIDE) {
        int beg = g_row[node], end = g_row[node + 1];

        if constexpr (F == 96) {
            constexpr int C4 = F / 4;  // 24 float4 cols; lanes 0..23 active
            const float4* H4 = (const float4*)HS;
            bool on = lane < C4;
            float4 acc = make_float4(0.f, 0.f, 0.f, 0.f);
            if (on) acc = H4[node * C4 + lane];  // self loop

            int j = beg;
            for (; j + 4 <= end; j += 4) {
                int s0 = g_csr[j + 0], s1 = g_csr[j + 1];
                int s2 = g_csr[j + 2], s3 = g_csr[j + 3];
                if (on) {
                    float4 v0 = H4[s0 * C4 + lane];
                    float4 v1 = H4[s1 * C4 + lane];
                    float4 v2 = H4[s2 * C4 + lane];
                    float4 v3 = H4[s3 * C4 + lane];
                    acc.x += (v0.x + v1.x) + (v2.x + v3.x);
                    acc.y += (v0.y + v1.y) + (v2.y + v3.y);
                    acc.z += (v0.z + v1.z) + (v2.z + v3.z);
                    acc.w += (v0.w + v1.w) + (v2.w + v3.w);
                }
            }
            for (; j < end; j++) {
                int s0 = g_csr[j];
                if (on) {
                    float4 v = H4[s0 * C4 + lane];
                    acc.x += v.x; acc.y += v.y; acc.z += v.z; acc.w += v.w;
                }
            }
            if (on) {
                float d = g_dis[node];
                float4 bb = ((const float4*)b)[lane];
                float4 o;
                if (ACT == 0) {
                    o.x = act_relu(fmaf(d, acc.x, bb.x));
                    o.y = act_relu(fmaf(d, acc.y, bb.y));
                    o.z = act_relu(fmaf(d, acc.z, bb.z));
                    o.w = act_relu(fmaf(d, acc.w, bb.w));
                } else {
                    o.x = act_sigmoid(fmaf(d, acc.x, bb.x));
                    o.y = act_sigmoid(fmaf(d, acc.y, bb.y));
                    o.z = act_sigmoid(fmaf(d, acc.z, bb.z));
                    o.w = act_sigmoid(fmaf(d, acc.w, bb.w));
                }
                ((float4*)OUT)[node * C4 + lane] = o;
            }
        } else {  // F == 64: float2 per lane, all 32 lanes active
            constexpr int C2 = F / 2;
            const float2* H2 = (const float2*)HS;
            float2 acc = H2[node * C2 + lane];  // self loop

            int j = beg;
            for (; j + 4 <= end; j += 4) {
                int s0 = g_csr[j + 0], s1 = g_csr[j + 1];
                int s2 = g_csr[j + 2], s3 = g_csr[j + 3];
                float2 v0 = H2[s0 * C2 + lane];
                float2 v1 = H2[s1 * C2 + lane];
                float2 v2 = H2[s2 * C2 + lane];
                float2 v3 = H2[s3 * C2 + lane];
                acc.x += (v0.x + v1.x) + (v2.x + v3.x);
                acc.y += (v0.y + v1.y) + (v2.y + v3.y);
            }
            for (; j < end; j++) {
                int s0 = g_csr[j];
                float2 v = H2[s0 * C2 + lane];
                acc.x += v.x; acc.y += v.y;
            }
            float d = g_dis[node];
            float2 bb = ((const float2*)b)[lane];
            float2 o;
            if (ACT == 0) {
                o.x = act_relu(fmaf(d, acc.x, bb.x));
                o.y = act_relu(fmaf(d, acc.y, bb.y));
            } else {
                o.x = act_sigmoid(fmaf(d, acc.x, bb.x));
                o.y = act_sigmoid(fmaf(d, acc.y, bb.y));
            }
            ((float2*)OUT)[node * C2 + lane] = o;
        }
    }
}

// ---------------- the single fused persistent kernel -----------------------
// smem: sWs (max 24KB) + sXs (max 12KB) + scan array (1KB) -> ~37.3KB
// __launch_bounds__(256,4): <=64 regs; 148 SMs * 4 = 592 >= 512 resident.
__global__ void __launch_bounds__(NT, 4)
k_fused(const float* __restrict__ x, const void* __restrict__ ep,
        const float* __restrict__ W1, const float* __restrict__ b1,
        const float* __restrict__ W2, const float* __restrict__ b2,
        float* __restrict__ out) {
    __shared__ float sWs[D1 * D2 > D0 * D1 ? D1 * D2 : D0 * D1];  // 6144
    __shared__ float sXs[32 * D1];                                 // 3072
    __shared__ int   sScan[NT];
    __shared__ int   s_nz;

    int t   = threadIdx.x;
    int blk = blockIdx.x;
    int gid = blk * NT + t;

    // ---- P0: zero histogram; block 0 detects edge dtype.
    // Values in [0,50000): little-endian int64 => odd 32-bit words of the
    // first 1024 entries are all 0; int32 => they are random edge ids.
    if (gid < NN) g_cnt[gid] = 0;
    int is64 = 0;
    if (blk == 0) {
        const int* e = (const int*)ep;
        int local = 0;
#pragma unroll
        for (int q = 0; q < 4; q++) local |= e[2 * (t * 4 + q) + 1];
        if (t == 0) s_nz = 0;
        __syncthreads();
        if (local) atomicOr(&s_nz, 1);
        __syncthreads();
        is64 = (s_nz == 0) ? 1 : 0;
        if (t == 0) g_bsum[0] = is64;   // reuse slot to publish (overwritten later)
    }
    gbar();
    if (blk != 0) is64 = __ldcg(&g_bsum[0]);
    gbar();  // everyone read is64 before g_bsum is reused by the scan

    // ---- P1: in-degree histogram (vector loads, 2 edges/iter)
    if (is64) {
        const longlong2* p = (const longlong2*)ep;
        for (int i = gid; i < NE / 2; i += GRID * NT) {
            longlong2 dd = p[NE / 2 + i];
            atomicAdd(&g_cnt[(int)dd.x], 1);
            atomicAdd(&g_cnt[(int)dd.y], 1);
        }
    } else {
        const int2* p = (const int2*)ep;
        for (int i = gid; i < NE / 2; i += GRID * NT) {
            int2 dd = p[NE / 2 + i];
            atomicAdd(&g_cnt[dd.x], 1);
            atomicAdd(&g_cnt[dd.y], 1);
        }
    }
    gbar();

    // ---- P2a: block-local inclusive scan of counts (one node per thread)
    int c = (gid < NN) ? __ldcg(&g_cnt[gid]) : 0;
    sScan[t] = c;
    __syncthreads();
#pragma unroll
    for (int off = 1; off < NT; off <<= 1) {
        int v = sScan[t];
        int a = (t >= off) ? sScan[t - off] : 0;
        __syncthreads();
        sScan[t] = v + a;
        __syncthreads();
    }
    int incl = sScan[t];
    if (t == NT - 1) g_bsum[blk] = incl;
    gbar();

    // ---- P2b: block 0 scans the GRID block totals (2 per thread)
    if (blk == 0) {
        int a  = __ldcg(&g_bsum[2 * t]);
        int b2v = __ldcg(&g_bsum[2 * t + 1]);
        int ps = a + b2v;
        sScan[t] = ps;
        __syncthreads();
#pragma unroll
        for (int off = 1; off < NT; off <<= 1) {
            int v = sScan[t];
            int ad = (t >= off) ? sScan[t - off] : 0;
            __syncthreads();
            sScan[t] = v + ad;
            __syncthreads();
        }
        int excl2 = sScan[t] - ps;
        g_bpre[2 * t]     = excl2;
        g_bpre[2 * t + 1] = excl2 + a;
    }
    gbar();

    // ---- P2c: write row/cur/dis
    if (gid < NN) {
        int base = __ldcg(&g_bpre[blk]);
        int excl = base + incl - c;
        g_row[gid] = excl;
        g_cur[gid] = excl;
        g_dis[gid] = rsqrtf((float)c + 1.0f);
    }
    if (gid == 0) g_row[NN] = NE;
    gbar();

    // ---- P3: CSR scatter
    if (is64) {
        const long long* p = (const long long*)ep;
        for (int e = gid; e < NE; e += GRID * NT) {
            int s = (int)p[e];
            int d = (int)p[NE + e];
            int pos = atomicAdd(&g_cur[d], 1);
            g_csr[pos] = s;
        }
    } else {
        const int* p = (const int*)ep;
        for (int e = gid; e < NE; e += GRID * NT) {
            int s = p[e];
            int d = p[NE + e];
            int pos = atomicAdd(&g_cur[d], 1);
            g_csr[pos] = s;
        }
    }
    gbar();

    // ---- P4: layer-1 GEMM  hs1 = (x @ W1) * dis
    gemm_phase<D0, D1>(x, W1, g_hs1, sWs, sXs);
    gbar();

    // ---- P5: layer-1 aggregation  h = relu(dis*(self+sum) + b1)
    agg_phase<D1, 0>(g_hs1, b1, g_h);
    gbar();

    // ---- P6: layer-2 GEMM  hs2 = (h @ W2) * dis
    gemm_phase<D1, D2>(g_h, W2, g_hs2, sWs, sXs);
    gbar();

    // ---- P7: layer-2 aggregation  out = sigmoid(dis*(self+sum) + b2)
    agg_phase<D2, 1>(g_hs2, b2, out);
}

// ---------------- launch: ONE kernel ---------------------------------------
extern "C" void kernel_launch(void* const* d_in, const int* in_sizes, int n_in,
                              void* d_out, int out_size) {
    const float* x  = (const float*)d_in[0];
    const void*  ei = d_in[1];
    const float* W1 = (const float*)d_in[2];
    const float* b1 = (const float*)d_in[3];
    const float* W2 = (const float*)d_in[4];
    const float* b2 = (const float*)d_in[5];
    float* out = (float*)d_out;

    k_fused<<<GRID, NT>>>(x, ei, W1, b1, W2, b2, out);
}